// round 3
// baseline (speedup 1.0000x reference)
#include <cuda_runtime.h>
#include <math.h>

#define HH 56
#define WW 56
#define HW 3136
#define CC 128
#define NB 8
#define NPTS 65536
#define TILE 64
#define TILES_PER_B (NPTS / TILE)      // 1024
#define NTILES (NB * TILES_PER_B)      // 8192
#define THREADS 256

// Transposed features: (B, H, W, C) so each bilinear tap is a contiguous 512B read.
__device__ float g_featT[NB * HW * CC];

// ---------------------------------------------------------------------------
// Kernel 1: transpose (B, C, HW) -> (B, HW, C)
// ---------------------------------------------------------------------------
__global__ void transpose_kernel(const float* __restrict__ src) {
    __shared__ float t[32][33];
    int st = blockIdx.x;   // 0..97  spatial tile (HW = 98*32)
    int ct = blockIdx.y;   // 0..3   channel tile (C = 4*32)
    int b  = blockIdx.z;   // 0..7
    int tx = threadIdx.x, ty = threadIdx.y;

    const float* sb = src     + (size_t)b * CC * HW;
    float*       db = g_featT + (size_t)b * HW * CC;

#pragma unroll
    for (int r = 0; r < 32; r += 8) {
        int c = ct * 32 + ty + r;
        int s = st * 32 + tx;
        t[ty + r][tx] = sb[(size_t)c * HW + s];
    }
    __syncthreads();
#pragma unroll
    for (int r = 0; r < 32; r += 8) {
        int s = st * 32 + ty + r;
        int c = ct * 32 + tx;
        db[(size_t)s * CC + c] = t[tx][ty + r];
    }
}

// ---------------------------------------------------------------------------
// Kernel 2: persistent fused decoder.
// Shared layout (floats):
//   W1s 16384 | W2s 4096 | W3s 4096 | W4s 64 | b1s 64 | b2s 64 | b3s 64 |
//   Bgs 192 | misc 64 (misc[0]=b4) | inp 16384 ([256][64] i-major) |
//   h1 4096 | h2 4096 | h3 4096   => 53760 floats = 215040 B
// ---------------------------------------------------------------------------
#define SMEM_FLOATS 53760
#define SMEM_BYTES  (SMEM_FLOATS * 4)

extern __shared__ float smem[];

__global__ __launch_bounds__(THREADS, 1)
void decoder_kernel(const float* __restrict__ points,
                    const float* __restrict__ kmat,
                    const float* __restrict__ rtm,
                    const float* __restrict__ Bg,
                    const float* __restrict__ W1, const float* __restrict__ b1,
                    const float* __restrict__ W2, const float* __restrict__ b2,
                    const float* __restrict__ W3, const float* __restrict__ b3,
                    const float* __restrict__ W4, const float* __restrict__ b4,
                    float* __restrict__ out)
{
    float* W1s  = smem;                 // 16384
    float* W2s  = W1s  + 16384;         // 4096
    float* W3s  = W2s  + 4096;          // 4096
    float* W4s  = W3s  + 4096;          // 64
    float* b1s  = W4s  + 64;            // 64
    float* b2s  = b1s  + 64;            // 64
    float* b3s  = b2s  + 64;            // 64
    float* Bgs  = b3s  + 64;            // 192
    float* misc = Bgs  + 192;           // 64
    float* inp  = misc + 64;            // 16384
    float* h1   = inp  + 16384;         // 4096
    float* h2   = h1   + 4096;          // 4096
    float* h3   = h2   + 4096;          // 4096

    const int tid = threadIdx.x;

    // Load weights once per (persistent) block.
    for (int i = tid; i < 16384; i += THREADS) W1s[i] = W1[i];
    for (int i = tid; i < 4096;  i += THREADS) { W2s[i] = W2[i]; W3s[i] = W3[i]; }
    if (tid < 64) { W4s[tid] = W4[tid]; b1s[tid] = b1[tid]; b2s[tid] = b2[tid]; b3s[tid] = b3[tid]; }
    for (int i = tid; i < 192; i += THREADS) Bgs[i] = Bg[i];
    if (tid == 0) misc[0] = b4[0];
    __syncthreads();

    const int sub  = tid & 3;       // stage-1: 4 threads per point
    const int psub = tid >> 2;      // stage-1 point id (0..63)
    const int p    = tid & 63;      // stage-2 point id
    const int jg   = tid >> 6;      // stage-2 output group (0..3)
    const int j0   = jg * 16;

    for (int tile = blockIdx.x; tile < NTILES; tile += gridDim.x) {
        const int b       = tile >> 10;
        const int n_base  = (tile & 1023) << 6;   // first point of tile in batch
        const int n       = n_base + psub;

        // ---- Stage 1: build input matrix inp[256][64] ----
        {
            const float* pp = points + ((size_t)b * NPTS + n) * 3;
            const float px = pp[0], py = pp[1], pz = pp[2];

            const float* R = rtm  + b * 12;
            const float* K = kmat + b * 9;
            float cam0 = R[0] * px + R[1] * py + R[2]  * pz + R[3];
            float cam1 = R[4] * px + R[5] * py + R[6]  * pz + R[7];
            float cam2 = R[8] * px + R[9] * py + R[10] * pz + R[11];
            float i0 = K[0] * cam0 + K[1] * cam1 + K[2] * cam2;
            float i1 = K[3] * cam0 + K[4] * cam1 + K[5] * cam2;
            float i2 = K[6] * cam0 + K[7] * cam1 + K[8] * cam2;
            float zz = i2 + 1e-8f;
            float u = i0 / zz;
            float v = i1 / zz;
            float valid = (i2 > 0.0f) ? 1.0f : 0.0f;
            // match reference's normalize/unnormalize chain op-for-op
            float un = (2.0f * u + 1.0f) / (float)WW - 1.0f;
            float vn = (2.0f * v + 1.0f) / (float)HH - 1.0f;
            float x = ((un + 1.0f) * (float)WW - 1.0f) * 0.5f;
            float y = ((vn + 1.0f) * (float)HH - 1.0f) * 0.5f;

            float x0f = floorf(x), y0f = floorf(y);
            float fx = x - x0f, fy = y - y0f;
            int ix0 = (int)x0f, iy0 = (int)y0f;
            int ix1 = ix0 + 1,  iy1 = iy0 + 1;
            float w00 = (1.0f - fx) * (1.0f - fy) * valid;
            float w10 = fx * (1.0f - fy) * valid;
            float w01 = (1.0f - fx) * fy * valid;
            float w11 = fx * fy * valid;
            bool i00 = ((unsigned)ix0 < (unsigned)WW) && ((unsigned)iy0 < (unsigned)HH);
            bool i10 = ((unsigned)ix1 < (unsigned)WW) && ((unsigned)iy0 < (unsigned)HH);
            bool i01 = ((unsigned)ix0 < (unsigned)WW) && ((unsigned)iy1 < (unsigned)HH);
            bool i11 = ((unsigned)ix1 < (unsigned)WW) && ((unsigned)iy1 < (unsigned)HH);

            const float* fb = g_featT + (size_t)b * (HW * CC);
            const int c0 = sub * 32;
            const int o00 = (iy0 * WW + ix0) * CC + c0;
            const int o10 = (iy0 * WW + ix1) * CC + c0;
            const int o01 = (iy1 * WW + ix0) * CC + c0;
            const int o11 = (iy1 * WW + ix1) * CC + c0;

#pragma unroll
            for (int kk = 0; kk < 8; ++kk) {
                float rx = 0.f, ry = 0.f, rz = 0.f, rw = 0.f;
                if (i00) {
                    float4 f = *(const float4*)(fb + o00 + kk * 4);
                    rx = fmaf(w00, f.x, rx); ry = fmaf(w00, f.y, ry);
                    rz = fmaf(w00, f.z, rz); rw = fmaf(w00, f.w, rw);
                }
                if (i10) {
                    float4 f = *(const float4*)(fb + o10 + kk * 4);
                    rx = fmaf(w10, f.x, rx); ry = fmaf(w10, f.y, ry);
                    rz = fmaf(w10, f.z, rz); rw = fmaf(w10, f.w, rw);
                }
                if (i01) {
                    float4 f = *(const float4*)(fb + o01 + kk * 4);
                    rx = fmaf(w01, f.x, rx); ry = fmaf(w01, f.y, ry);
                    rz = fmaf(w01, f.z, rz); rw = fmaf(w01, f.w, rw);
                }
                if (i11) {
                    float4 f = *(const float4*)(fb + o11 + kk * 4);
                    rx = fmaf(w11, f.x, rx); ry = fmaf(w11, f.y, ry);
                    rz = fmaf(w11, f.z, rz); rw = fmaf(w11, f.w, rw);
                }
                int c = c0 + kk * 4;
                inp[(c + 0) * 64 + psub] = rx;
                inp[(c + 1) * 64 + psub] = ry;
                inp[(c + 2) * 64 + psub] = rz;
                inp[(c + 3) * 64 + psub] = rw;
            }

            // Fourier features: sin at rows 128..191, cos at 192..255
#pragma unroll
            for (int m = 0; m < 16; ++m) {
                int mm = sub * 16 + m;
                float pr = 6.283185307179586f *
                           (px * Bgs[mm * 3 + 0] + py * Bgs[mm * 3 + 1] + pz * Bgs[mm * 3 + 2]);
                inp[(128 + mm) * 64 + psub] = __sinf(pr);
                inp[(192 + mm) * 64 + psub] = __cosf(pr);
            }
        }
        __syncthreads();

        // ---- Layer 1: [64 x 256] @ [256 x 64] + relu -> h1 ----
        {
            float acc[16];
#pragma unroll
            for (int k2 = 0; k2 < 16; ++k2) acc[k2] = b1s[j0 + k2];
#pragma unroll 4
            for (int i = 0; i < 256; ++i) {
                float a = inp[i * 64 + p];
                const float4* wr = (const float4*)(W1s + i * 64 + j0);
                float4 wA = wr[0], wB = wr[1], wC = wr[2], wD = wr[3];
                acc[0]  = fmaf(a, wA.x, acc[0]);  acc[1]  = fmaf(a, wA.y, acc[1]);
                acc[2]  = fmaf(a, wA.z, acc[2]);  acc[3]  = fmaf(a, wA.w, acc[3]);
                acc[4]  = fmaf(a, wB.x, acc[4]);  acc[5]  = fmaf(a, wB.y, acc[5]);
                acc[6]  = fmaf(a, wB.z, acc[6]);  acc[7]  = fmaf(a, wB.w, acc[7]);
                acc[8]  = fmaf(a, wC.x, acc[8]);  acc[9]  = fmaf(a, wC.y, acc[9]);
                acc[10] = fmaf(a, wC.z, acc[10]); acc[11] = fmaf(a, wC.w, acc[11]);
                acc[12] = fmaf(a, wD.x, acc[12]); acc[13] = fmaf(a, wD.y, acc[13]);
                acc[14] = fmaf(a, wD.z, acc[14]); acc[15] = fmaf(a, wD.w, acc[15]);
            }
#pragma unroll
            for (int k2 = 0; k2 < 16; ++k2)
                h1[(j0 + k2) * 64 + p] = fmaxf(acc[k2], 0.0f);
        }
        __syncthreads();

        // ---- Layer 2: h1 -> h2 ----
        {
            float acc[16];
#pragma unroll
            for (int k2 = 0; k2 < 16; ++k2) acc[k2] = b2s[j0 + k2];
#pragma unroll 4
            for (int i = 0; i < 64; ++i) {
                float a = h1[i * 64 + p];
                const float4* wr = (const float4*)(W2s + i * 64 + j0);
                float4 wA = wr[0], wB = wr[1], wC = wr[2], wD = wr[3];
                acc[0]  = fmaf(a, wA.x, acc[0]);  acc[1]  = fmaf(a, wA.y, acc[1]);
                acc[2]  = fmaf(a, wA.z, acc[2]);  acc[3]  = fmaf(a, wA.w, acc[3]);
                acc[4]  = fmaf(a, wB.x, acc[4]);  acc[5]  = fmaf(a, wB.y, acc[5]);
                acc[6]  = fmaf(a, wB.z, acc[6]);  acc[7]  = fmaf(a, wB.w, acc[7]);
                acc[8]  = fmaf(a, wC.x, acc[8]);  acc[9]  = fmaf(a, wC.y, acc[9]);
                acc[10] = fmaf(a, wC.z, acc[10]); acc[11] = fmaf(a, wC.w, acc[11]);
                acc[12] = fmaf(a, wD.x, acc[12]); acc[13] = fmaf(a, wD.y, acc[13]);
                acc[14] = fmaf(a, wD.z, acc[14]); acc[15] = fmaf(a, wD.w, acc[15]);
            }
#pragma unroll
            for (int k2 = 0; k2 < 16; ++k2)
                h2[(j0 + k2) * 64 + p] = fmaxf(acc[k2], 0.0f);
        }
        __syncthreads();

        // ---- Layer 3: h2 -> h3 ----
        {
            float acc[16];
#pragma unroll
            for (int k2 = 0; k2 < 16; ++k2) acc[k2] = b3s[j0 + k2];
#pragma unroll 4
            for (int i = 0; i < 64; ++i) {
                float a = h2[i * 64 + p];
                const float4* wr = (const float4*)(W3s + i * 64 + j0);
                float4 wA = wr[0], wB = wr[1], wC = wr[2], wD = wr[3];
                acc[0]  = fmaf(a, wA.x, acc[0]);  acc[1]  = fmaf(a, wA.y, acc[1]);
                acc[2]  = fmaf(a, wA.z, acc[2]);  acc[3]  = fmaf(a, wA.w, acc[3]);
                acc[4]  = fmaf(a, wB.x, acc[4]);  acc[5]  = fmaf(a, wB.y, acc[5]);
                acc[6]  = fmaf(a, wB.z, acc[6]);  acc[7]  = fmaf(a, wB.w, acc[7]);
                acc[8]  = fmaf(a, wC.x, acc[8]);  acc[9]  = fmaf(a, wC.y, acc[9]);
                acc[10] = fmaf(a, wC.z, acc[10]); acc[11] = fmaf(a, wC.w, acc[11]);
                acc[12] = fmaf(a, wD.x, acc[12]); acc[13] = fmaf(a, wD.y, acc[13]);
                acc[14] = fmaf(a, wD.z, acc[14]); acc[15] = fmaf(a, wD.w, acc[15]);
            }
#pragma unroll
            for (int k2 = 0; k2 < 16; ++k2)
                h3[(j0 + k2) * 64 + p] = fmaxf(acc[k2], 0.0f);
        }
        __syncthreads();

        // ---- Layer 4: h3 @ W4 + b4 -> out ----
        if (tid < 64) {
            float s = misc[0];
#pragma unroll 8
            for (int j = 0; j < 64; ++j)
                s = fmaf(h3[j * 64 + tid], W4s[j], s);
            out[(size_t)b * NPTS + n_base + tid] = s;
        }
        __syncthreads();
    }
}

// ---------------------------------------------------------------------------
extern "C" void kernel_launch(void* const* d_in, const int* in_sizes, int n_in,
                              void* d_out, int out_size) {
    const float* features = (const float*)d_in[0];
    const float* points   = (const float*)d_in[1];
    const float* kmat     = (const float*)d_in[2];
    const float* rtm      = (const float*)d_in[3];
    const float* Bg       = (const float*)d_in[4];
    const float* W1       = (const float*)d_in[5];
    const float* b1       = (const float*)d_in[6];
    const float* W2       = (const float*)d_in[7];
    const float* b2       = (const float*)d_in[8];
    const float* W3       = (const float*)d_in[9];
    const float* b3       = (const float*)d_in[10];
    const float* W4       = (const float*)d_in[11];
    const float* b4       = (const float*)d_in[12];
    float* out            = (float*)d_out;

    cudaFuncSetAttribute(decoder_kernel,
                         cudaFuncAttributeMaxDynamicSharedMemorySize, SMEM_BYTES);

    dim3 tgrid(98, 4, 8);
    dim3 tblk(32, 8);
    transpose_kernel<<<tgrid, tblk>>>(features);

    int dev = 0, sms = 148;
    cudaGetDevice(&dev);
    cudaDeviceGetAttribute(&sms, cudaDevAttrMultiProcessorCount, dev);
    if (sms <= 0) sms = 148;

    decoder_kernel<<<sms, THREADS, SMEM_BYTES>>>(
        points, kmat, rtm, Bg, W1, b1, W2, b2, W3, b3, W4, b4, out);
}

// round 6
// speedup vs baseline: 1.0013x; 1.0013x over previous
#include <cuda_runtime.h>
#include <math.h>

#define HH 56
#define WW 56
#define HW 3136
#define CC 128
#define NB 8
#define NPTS 65536
#define TILE 64
#define TILES_PER_B (NPTS / TILE)      // 1024
#define NTILES (NB * TILES_PER_B)      // 8192
#define THREADS 256

// Transposed features: (B, H, W, C) so each bilinear tap is a contiguous 512B read.
__device__ float g_featT[NB * HW * CC];

// ---------------------------------------------------------------------------
// Kernel 1: transpose (B, C, HW) -> (B, HW, C)
// ---------------------------------------------------------------------------
__global__ void transpose_kernel(const float* __restrict__ src) {
    __shared__ float t[32][33];
    int st = blockIdx.x;   // 0..97  spatial tile (HW = 98*32)
    int ct = blockIdx.y;   // 0..3   channel tile (C = 4*32)
    int b  = blockIdx.z;   // 0..7
    int tx = threadIdx.x, ty = threadIdx.y;

    const float* sb = src     + (size_t)b * CC * HW;
    float*       db = g_featT + (size_t)b * HW * CC;

#pragma unroll
    for (int r = 0; r < 32; r += 8) {
        int c = ct * 32 + ty + r;
        int s = st * 32 + tx;
        t[ty + r][tx] = sb[(size_t)c * HW + s];
    }
    __syncthreads();
#pragma unroll
    for (int r = 0; r < 32; r += 8) {
        int s = st * 32 + ty + r;
        int c = ct * 32 + tx;
        db[(size_t)s * CC + c] = t[tx][ty + r];
    }
}

// ---------------------------------------------------------------------------
// Kernel 2: persistent fused decoder.
// Shared layout (floats):
//   W1s 16384 | W2s 4096 | W3s 4096 | W4s 64 | b1s 64 | b2s 64 | b3s 64 |
//   Bgs 192 | misc 64 (misc[0]=b4) | inp 16384 ([256][64] i-major) |
//   h1 4096 | h2 4096 | h3 4096   => 53760 floats = 215040 B
// ---------------------------------------------------------------------------
#define SMEM_FLOATS 53760
#define SMEM_BYTES  (SMEM_FLOATS * 4)

extern __shared__ float smem[];

__global__ __launch_bounds__(THREADS, 1)
void decoder_kernel(const float* __restrict__ points,
                    const float* __restrict__ kmat,
                    const float* __restrict__ rtm,
                    const float* __restrict__ Bg,
                    const float* __restrict__ W1, const float* __restrict__ b1,
                    const float* __restrict__ W2, const float* __restrict__ b2,
                    const float* __restrict__ W3, const float* __restrict__ b3,
                    const float* __restrict__ W4, const float* __restrict__ b4,
                    float* __restrict__ out)
{
    float* W1s  = smem;                 // 16384
    float* W2s  = W1s  + 16384;         // 4096
    float* W3s  = W2s  + 4096;          // 4096
    float* W4s  = W3s  + 4096;          // 64
    float* b1s  = W4s  + 64;            // 64
    float* b2s  = b1s  + 64;            // 64
    float* b3s  = b2s  + 64;            // 64
    float* Bgs  = b3s  + 64;            // 192
    float* misc = Bgs  + 192;           // 64
    float* inp  = misc + 64;            // 16384
    float* h1   = inp  + 16384;         // 4096
    float* h2   = h1   + 4096;          // 4096
    float* h3   = h2   + 4096;          // 4096

    const int tid = threadIdx.x;

    // Load weights once per (persistent) block.
    for (int i = tid; i < 16384; i += THREADS) W1s[i] = W1[i];
    for (int i = tid; i < 4096;  i += THREADS) { W2s[i] = W2[i]; W3s[i] = W3[i]; }
    if (tid < 64) { W4s[tid] = W4[tid]; b1s[tid] = b1[tid]; b2s[tid] = b2[tid]; b3s[tid] = b3[tid]; }
    for (int i = tid; i < 192; i += THREADS) Bgs[i] = Bg[i];
    if (tid == 0) misc[0] = b4[0];
    __syncthreads();

    const int sub  = tid & 3;       // stage-1: 4 threads per point
    const int psub = tid >> 2;      // stage-1 point id (0..63)
    const int p    = tid & 63;      // stage-2 point id
    const int jg   = tid >> 6;      // stage-2 output group (0..3)
    const int j0   = jg * 16;

    for (int tile = blockIdx.x; tile < NTILES; tile += gridDim.x) {
        const int b       = tile >> 10;
        const int n_base  = (tile & 1023) << 6;   // first point of tile in batch
        const int n       = n_base + psub;

        // ---- Stage 1: build input matrix inp[256][64] ----
        {
            const float* pp = points + ((size_t)b * NPTS + n) * 3;
            const float px = pp[0], py = pp[1], pz = pp[2];

            const float* R = rtm  + b * 12;
            const float* K = kmat + b * 9;
            float cam0 = R[0] * px + R[1] * py + R[2]  * pz + R[3];
            float cam1 = R[4] * px + R[5] * py + R[6]  * pz + R[7];
            float cam2 = R[8] * px + R[9] * py + R[10] * pz + R[11];
            float i0 = K[0] * cam0 + K[1] * cam1 + K[2] * cam2;
            float i1 = K[3] * cam0 + K[4] * cam1 + K[5] * cam2;
            float i2 = K[6] * cam0 + K[7] * cam1 + K[8] * cam2;
            float zz = i2 + 1e-8f;
            float u = i0 / zz;
            float v = i1 / zz;
            float valid = (i2 > 0.0f) ? 1.0f : 0.0f;
            // match reference's normalize/unnormalize chain op-for-op
            float un = (2.0f * u + 1.0f) / (float)WW - 1.0f;
            float vn = (2.0f * v + 1.0f) / (float)HH - 1.0f;
            float x = ((un + 1.0f) * (float)WW - 1.0f) * 0.5f;
            float y = ((vn + 1.0f) * (float)HH - 1.0f) * 0.5f;

            float x0f = floorf(x), y0f = floorf(y);
            float fx = x - x0f, fy = y - y0f;
            int ix0 = (int)x0f, iy0 = (int)y0f;
            int ix1 = ix0 + 1,  iy1 = iy0 + 1;
            float w00 = (1.0f - fx) * (1.0f - fy) * valid;
            float w10 = fx * (1.0f - fy) * valid;
            float w01 = (1.0f - fx) * fy * valid;
            float w11 = fx * fy * valid;
            bool i00 = ((unsigned)ix0 < (unsigned)WW) && ((unsigned)iy0 < (unsigned)HH);
            bool i10 = ((unsigned)ix1 < (unsigned)WW) && ((unsigned)iy0 < (unsigned)HH);
            bool i01 = ((unsigned)ix0 < (unsigned)WW) && ((unsigned)iy1 < (unsigned)HH);
            bool i11 = ((unsigned)ix1 < (unsigned)WW) && ((unsigned)iy1 < (unsigned)HH);

            const float* fb = g_featT + (size_t)b * (HW * CC);
            const int c0 = sub * 32;
            const int o00 = (iy0 * WW + ix0) * CC + c0;
            const int o10 = (iy0 * WW + ix1) * CC + c0;
            const int o01 = (iy1 * WW + ix0) * CC + c0;
            const int o11 = (iy1 * WW + ix1) * CC + c0;

#pragma unroll
            for (int kk = 0; kk < 8; ++kk) {
                float rx = 0.f, ry = 0.f, rz = 0.f, rw = 0.f;
                if (i00) {
                    float4 f = *(const float4*)(fb + o00 + kk * 4);
                    rx = fmaf(w00, f.x, rx); ry = fmaf(w00, f.y, ry);
                    rz = fmaf(w00, f.z, rz); rw = fmaf(w00, f.w, rw);
                }
                if (i10) {
                    float4 f = *(const float4*)(fb + o10 + kk * 4);
                    rx = fmaf(w10, f.x, rx); ry = fmaf(w10, f.y, ry);
                    rz = fmaf(w10, f.z, rz); rw = fmaf(w10, f.w, rw);
                }
                if (i01) {
                    float4 f = *(const float4*)(fb + o01 + kk * 4);
                    rx = fmaf(w01, f.x, rx); ry = fmaf(w01, f.y, ry);
                    rz = fmaf(w01, f.z, rz); rw = fmaf(w01, f.w, rw);
                }
                if (i11) {
                    float4 f = *(const float4*)(fb + o11 + kk * 4);
                    rx = fmaf(w11, f.x, rx); ry = fmaf(w11, f.y, ry);
                    rz = fmaf(w11, f.z, rz); rw = fmaf(w11, f.w, rw);
                }
                int c = c0 + kk * 4;
                inp[(c + 0) * 64 + psub] = rx;
                inp[(c + 1) * 64 + psub] = ry;
                inp[(c + 2) * 64 + psub] = rz;
                inp[(c + 3) * 64 + psub] = rw;
            }

            // Fourier features: sin at rows 128..191, cos at 192..255
#pragma unroll
            for (int m = 0; m < 16; ++m) {
                int mm = sub * 16 + m;
                float pr = 6.283185307179586f *
                           (px * Bgs[mm * 3 + 0] + py * Bgs[mm * 3 + 1] + pz * Bgs[mm * 3 + 2]);
                inp[(128 + mm) * 64 + psub] = __sinf(pr);
                inp[(192 + mm) * 64 + psub] = __cosf(pr);
            }
        }
        __syncthreads();

        // ---- Layer 1: [64 x 256] @ [256 x 64] + relu -> h1 ----
        {
            float acc[16];
#pragma unroll
            for (int k2 = 0; k2 < 16; ++k2) acc[k2] = b1s[j0 + k2];
#pragma unroll 4
            for (int i = 0; i < 256; ++i) {
                float a = inp[i * 64 + p];
                const float4* wr = (const float4*)(W1s + i * 64 + j0);
                float4 wA = wr[0], wB = wr[1], wC = wr[2], wD = wr[3];
                acc[0]  = fmaf(a, wA.x, acc[0]);  acc[1]  = fmaf(a, wA.y, acc[1]);
                acc[2]  = fmaf(a, wA.z, acc[2]);  acc[3]  = fmaf(a, wA.w, acc[3]);
                acc[4]  = fmaf(a, wB.x, acc[4]);  acc[5]  = fmaf(a, wB.y, acc[5]);
                acc[6]  = fmaf(a, wB.z, acc[6]);  acc[7]  = fmaf(a, wB.w, acc[7]);
                acc[8]  = fmaf(a, wC.x, acc[8]);  acc[9]  = fmaf(a, wC.y, acc[9]);
                acc[10] = fmaf(a, wC.z, acc[10]); acc[11] = fmaf(a, wC.w, acc[11]);
                acc[12] = fmaf(a, wD.x, acc[12]); acc[13] = fmaf(a, wD.y, acc[13]);
                acc[14] = fmaf(a, wD.z, acc[14]); acc[15] = fmaf(a, wD.w, acc[15]);
            }
#pragma unroll
            for (int k2 = 0; k2 < 16; ++k2)
                h1[(j0 + k2) * 64 + p] = fmaxf(acc[k2], 0.0f);
        }
        __syncthreads();

        // ---- Layer 2: h1 -> h2 ----
        {
            float acc[16];
#pragma unroll
            for (int k2 = 0; k2 < 16; ++k2) acc[k2] = b2s[j0 + k2];
#pragma unroll 4
            for (int i = 0; i < 64; ++i) {
                float a = h1[i * 64 + p];
                const float4* wr = (const float4*)(W2s + i * 64 + j0);
                float4 wA = wr[0], wB = wr[1], wC = wr[2], wD = wr[3];
                acc[0]  = fmaf(a, wA.x, acc[0]);  acc[1]  = fmaf(a, wA.y, acc[1]);
                acc[2]  = fmaf(a, wA.z, acc[2]);  acc[3]  = fmaf(a, wA.w, acc[3]);
                acc[4]  = fmaf(a, wB.x, acc[4]);  acc[5]  = fmaf(a, wB.y, acc[5]);
                acc[6]  = fmaf(a, wB.z, acc[6]);  acc[7]  = fmaf(a, wB.w, acc[7]);
                acc[8]  = fmaf(a, wC.x, acc[8]);  acc[9]  = fmaf(a, wC.y, acc[9]);
                acc[10] = fmaf(a, wC.z, acc[10]); acc[11] = fmaf(a, wC.w, acc[11]);
                acc[12] = fmaf(a, wD.x, acc[12]); acc[13] = fmaf(a, wD.y, acc[13]);
                acc[14] = fmaf(a, wD.z, acc[14]); acc[15] = fmaf(a, wD.w, acc[15]);
            }
#pragma unroll
            for (int k2 = 0; k2 < 16; ++k2)
                h2[(j0 + k2) * 64 + p] = fmaxf(acc[k2], 0.0f);
        }
        __syncthreads();

        // ---- Layer 3: h2 -> h3 ----
        {
            float acc[16];
#pragma unroll
            for (int k2 = 0; k2 < 16; ++k2) acc[k2] = b3s[j0 + k2];
#pragma unroll 4
            for (int i = 0; i < 64; ++i) {
                float a = h2[i * 64 + p];
                const float4* wr = (const float4*)(W3s + i * 64 + j0);
                float4 wA = wr[0], wB = wr[1], wC = wr[2], wD = wr[3];
                acc[0]  = fmaf(a, wA.x, acc[0]);  acc[1]  = fmaf(a, wA.y, acc[1]);
                acc[2]  = fmaf(a, wA.z, acc[2]);  acc[3]  = fmaf(a, wA.w, acc[3]);
                acc[4]  = fmaf(a, wB.x, acc[4]);  acc[5]  = fmaf(a, wB.y, acc[5]);
                acc[6]  = fmaf(a, wB.z, acc[6]);  acc[7]  = fmaf(a, wB.w, acc[7]);
                acc[8]  = fmaf(a, wC.x, acc[8]);  acc[9]  = fmaf(a, wC.y, acc[9]);
                acc[10] = fmaf(a, wC.z, acc[10]); acc[11] = fmaf(a, wC.w, acc[11]);
                acc[12] = fmaf(a, wD.x, acc[12]); acc[13] = fmaf(a, wD.y, acc[13]);
                acc[14] = fmaf(a, wD.z, acc[14]); acc[15] = fmaf(a, wD.w, acc[15]);
            }
#pragma unroll
            for (int k2 = 0; k2 < 16; ++k2)
                h3[(j0 + k2) * 64 + p] = fmaxf(acc[k2], 0.0f);
        }
        __syncthreads();

        // ---- Layer 4: h3 @ W4 + b4 -> out ----
        if (tid < 64) {
            float s = misc[0];
#pragma unroll 8
            for (int j = 0; j < 64; ++j)
                s = fmaf(h3[j * 64 + tid], W4s[j], s);
            out[(size_t)b * NPTS + n_base + tid] = s;
        }
        __syncthreads();
    }
}

// ---------------------------------------------------------------------------
extern "C" void kernel_launch(void* const* d_in, const int* in_sizes, int n_in,
                              void* d_out, int out_size) {
    const float* features = (const float*)d_in[0];
    const float* points   = (const float*)d_in[1];
    const float* kmat     = (const float*)d_in[2];
    const float* rtm      = (const float*)d_in[3];
    const float* Bg       = (const float*)d_in[4];
    const float* W1       = (const float*)d_in[5];
    const float* b1       = (const float*)d_in[6];
    const float* W2       = (const float*)d_in[7];
    const float* b2       = (const float*)d_in[8];
    const float* W3       = (const float*)d_in[9];
    const float* b3       = (const float*)d_in[10];
    const float* W4       = (const float*)d_in[11];
    const float* b4       = (const float*)d_in[12];
    float* out            = (float*)d_out;

    cudaFuncSetAttribute(decoder_kernel,
                         cudaFuncAttributeMaxDynamicSharedMemorySize, SMEM_BYTES);

    dim3 tgrid(98, 4, 8);
    dim3 tblk(32, 8);
    transpose_kernel<<<tgrid, tblk>>>(features);

    int dev = 0, sms = 148;
    cudaGetDevice(&dev);
    cudaDeviceGetAttribute(&sms, cudaDevAttrMultiProcessorCount, dev);
    if (sms <= 0) sms = 148;

    decoder_kernel<<<sms, THREADS, SMEM_BYTES>>>(
        points, kmat, rtm, Bg, W1, b1, W2, b2, W3, b3, W4, b4, out);
}

// round 7
// speedup vs baseline: 2.5429x; 2.5395x over previous
#include <cuda_runtime.h>
#include <cuda_bf16.h>
#include <math.h>
#include <stdint.h>

#define HH 56
#define WW 56
#define HWSZ 3136
#define NB 8
#define NPTS 65536
#define THREADS 256
#define NTILES 4096            // 524288 points / 128 per tile

// Precomputed G[b][hw][64] = sum_c feat[b][c][hw] * W1[c][n]  (img half of layer 1)
__device__ float g_G[NB * HWSZ * 64];

extern __shared__ char dsm[];

// ---------------- smem map (decoder), byte offsets ----------------
#define W1FH 0          // [64 n][128 k] bf16 hi, swizzled, 16 chunks/row
#define W1FL 16384
#define W2HS 32768      // [64][64] bf16, 8 chunks/row
#define W2LS 40960
#define W3HS 49152
#define W3LS 57344
#define AHS  65536      // A tile [128 pts][128 cols] bf16 hi (fourier), 16 chunks/row
#define ALS  98304
#define GSS  131072     // Gblend [128][68] f32 (padded stride) = 34816
#define B1S  165888
#define B2S  166144
#define B3S  166400
#define W4S  166656
#define B4S  166912
#define BGS  166928     // 192 floats
#define SMEMB 167808

#define LDSM4(R, A) asm volatile("ldmatrix.sync.aligned.m8n8.x4.shared.b16 {%0,%1,%2,%3}, [%4];" \
  : "=r"((R)[0]), "=r"((R)[1]), "=r"((R)[2]), "=r"((R)[3]) : "r"(A))

#define MMA(D, A, B0, B1) asm volatile( \
  "mma.sync.aligned.m16n8k16.row.col.f32.bf16.bf16.f32 {%0,%1,%2,%3}, {%4,%5,%6,%7}, {%8,%9}, {%0,%1,%2,%3};" \
  : "+f"((D)[0]), "+f"((D)[1]), "+f"((D)[2]), "+f"((D)[3]) \
  : "r"((A)[0]), "r"((A)[1]), "r"((A)[2]), "r"((A)[3]), "r"(B0), "r"(B1))

__device__ __forceinline__ void hilo(float a, float b, uint32_t& h, uint32_t& l) {
  __nv_bfloat16 ha = __float2bfloat16(a), hb = __float2bfloat16(b);
  __nv_bfloat162 hp; hp.x = ha; hp.y = hb;
  __nv_bfloat162 lp;
  lp.x = __float2bfloat16(a - __bfloat162float(ha));
  lp.y = __float2bfloat16(b - __bfloat162float(hb));
  h = *(uint32_t*)&hp; l = *(uint32_t*)&lp;
}

// Build next-layer A fragments (hi/lo) from C frags + bias + relu.
// C frag n-tiles (2kk, 2kk+1) concatenated == A frag k-tile kk.
__device__ __forceinline__ void build_afr(const float d[8][4], const float* bs, int q,
                                          uint32_t ah[4][4], uint32_t al[4][4]) {
#pragma unroll
  for (int kk = 0; kk < 4; kk++) {
    const int j0 = 2 * kk, j1 = 2 * kk + 1;
    float ba = bs[8*j0+2*q], bb = bs[8*j0+2*q+1];
    float bc = bs[8*j1+2*q], bd = bs[8*j1+2*q+1];
    hilo(fmaxf(d[j0][0]+ba,0.f), fmaxf(d[j0][1]+bb,0.f), ah[kk][0], al[kk][0]);
    hilo(fmaxf(d[j0][2]+ba,0.f), fmaxf(d[j0][3]+bb,0.f), ah[kk][1], al[kk][1]);
    hilo(fmaxf(d[j1][0]+bc,0.f), fmaxf(d[j1][1]+bd,0.f), ah[kk][2], al[kk][2]);
    hilo(fmaxf(d[j1][2]+bc,0.f), fmaxf(d[j1][3]+bd,0.f), ah[kk][3], al[kk][3]);
  }
}

// 64x64 layer: D = Ah*Wh + Al*Wh + Ah*Wl, K=64 (4 k-steps), N=64 (4 n-pairs)
__device__ __forceinline__ void layer64(float d[8][4], const uint32_t ah[4][4], const uint32_t al[4][4],
                                        uint32_t sb, uint32_t baseH, uint32_t baseL, int bnu, int bkb) {
#pragma unroll
  for (int j = 0; j < 8; j++)
#pragma unroll
    for (int e = 0; e < 4; e++) d[j][e] = 0.f;
#pragma unroll
  for (int kk = 0; kk < 4; kk++) {
    const int kch = (kk * 16 + bkb) >> 3;
#pragma unroll
    for (int jp = 0; jp < 4; jp++) {
      const int n = jp * 16 + bnu;
      const uint32_t off = (uint32_t)((n << 3) + (kch ^ (n & 7))) * 16u;
      uint32_t wh[4], wl[4];
      LDSM4(wh, sb + baseH + off);
      LDSM4(wl, sb + baseL + off);
      MMA(d[2*jp],   ah[kk], wh[0], wh[1]);
      MMA(d[2*jp+1], ah[kk], wh[2], wh[3]);
      MMA(d[2*jp],   al[kk], wh[0], wh[1]);
      MMA(d[2*jp+1], al[kk], wh[2], wh[3]);
      MMA(d[2*jp],   ah[kk], wl[0], wl[1]);
      MMA(d[2*jp+1], ah[kk], wl[2], wl[3]);
    }
  }
}

// ---------------------------------------------------------------------------
// Kernel 1: G precompute. grid = 196, block = 256. dyn smem 98304.
// ---------------------------------------------------------------------------
__global__ __launch_bounds__(THREADS, 1)
void g_precomp_kernel(const float* __restrict__ feat, const float* __restrict__ W1) {
  float* fs = (float*)dsm;          // [128 c][128 row]
  float* ws = fs + 128 * 128;       // [128 c][64 n]
  const int tid = threadIdx.x;
  const int R0 = blockIdx.x * 128;
  for (int idx = tid; idx < 128 * 128; idx += THREADS) {
    int c = idx >> 7, i = idx & 127;
    int row = R0 + i, b = row / HWSZ, hw = row - b * HWSZ;
    fs[c * 128 + i] = feat[((size_t)b * 128 + c) * HWSZ + hw];
  }
  for (int idx = tid; idx < 128 * 64; idx += THREADS) ws[idx] = W1[idx];
  __syncthreads();
  const int r0 = (tid >> 3) * 4, c0 = (tid & 7) * 8;
  float acc[4][8];
#pragma unroll
  for (int a = 0; a < 4; a++)
#pragma unroll
    for (int j = 0; j < 8; j++) acc[a][j] = 0.f;
  for (int c = 0; c < 128; c++) {
    float a0 = fs[c*128+r0], a1 = fs[c*128+r0+1], a2 = fs[c*128+r0+2], a3 = fs[c*128+r0+3];
#pragma unroll
    for (int j = 0; j < 8; j++) {
      float w = ws[c*64 + c0 + j];
      acc[0][j] = fmaf(a0, w, acc[0][j]);
      acc[1][j] = fmaf(a1, w, acc[1][j]);
      acc[2][j] = fmaf(a2, w, acc[2][j]);
      acc[3][j] = fmaf(a3, w, acc[3][j]);
    }
  }
#pragma unroll
  for (int a = 0; a < 4; a++) {
    float* dst = g_G + (size_t)(R0 + r0 + a) * 64 + c0;
#pragma unroll
    for (int j = 0; j < 8; j += 4)
      *(float4*)(dst + j) = make_float4(acc[a][j], acc[a][j+1], acc[a][j+2], acc[a][j+3]);
  }
}

// ---------------------------------------------------------------------------
// Kernel 2: persistent tensor-core decoder. tile = 128 points, warp = 16 pts.
// ---------------------------------------------------------------------------
__global__ __launch_bounds__(THREADS, 1)
void decoder_kernel(const float* __restrict__ points,
                    const float* __restrict__ kmat,
                    const float* __restrict__ rtm,
                    const float* __restrict__ Bg,
                    const float* __restrict__ W1, const float* __restrict__ b1,
                    const float* __restrict__ W2, const float* __restrict__ b2,
                    const float* __restrict__ W3, const float* __restrict__ b3,
                    const float* __restrict__ W4, const float* __restrict__ b4,
                    float* __restrict__ out)
{
  const int tid = threadIdx.x;
  const uint32_t sb = (uint32_t)__cvta_generic_to_shared(dsm);

  // ---- one-time weight prep ----
  for (int i = tid; i < 8192; i += THREADS) {        // W1 fourier half -> [n][k] hi/lo
    int k = i >> 6, n = i & 63;
    float v = W1[(128 + k) * 64 + n];
    __nv_bfloat16 h = __float2bfloat16(v);
    uint32_t off = (uint32_t)((n << 4) + ((k >> 3) ^ (n & 7))) * 16u + (uint32_t)(k & 7) * 2u;
    *(__nv_bfloat16*)(dsm + W1FH + off) = h;
    *(__nv_bfloat16*)(dsm + W1FL + off) = __float2bfloat16(v - __bfloat162float(h));
  }
  for (int i = tid; i < 4096; i += THREADS) {        // W2, W3 -> [n][k] hi/lo
    int k = i >> 6, n = i & 63;
    uint32_t off = (uint32_t)((n << 3) + ((k >> 3) ^ (n & 7))) * 16u + (uint32_t)(k & 7) * 2u;
    float v2 = W2[i];
    __nv_bfloat16 h2 = __float2bfloat16(v2);
    *(__nv_bfloat16*)(dsm + W2HS + off) = h2;
    *(__nv_bfloat16*)(dsm + W2LS + off) = __float2bfloat16(v2 - __bfloat162float(h2));
    float v3 = W3[i];
    __nv_bfloat16 h3 = __float2bfloat16(v3);
    *(__nv_bfloat16*)(dsm + W3HS + off) = h3;
    *(__nv_bfloat16*)(dsm + W3LS + off) = __float2bfloat16(v3 - __bfloat162float(h3));
  }
  if (tid < 64) {
    ((float*)(dsm + B1S))[tid] = b1[tid];
    ((float*)(dsm + B2S))[tid] = b2[tid];
    ((float*)(dsm + B3S))[tid] = b3[tid];
    ((float*)(dsm + W4S))[tid] = W4[tid];
  }
  if (tid == 0) ((float*)(dsm + B4S))[0] = b4[0];
  for (int i = tid; i < 192; i += THREADS)
    ((float*)(dsm + BGS))[i] = Bg[i] * 6.283185307179586f;
  __syncthreads();

  const float* b1s = (const float*)(dsm + B1S);
  const float* b2s = (const float*)(dsm + B2S);
  const float* b3s = (const float*)(dsm + B3S);
  const float* W4s = (const float*)(dsm + W4S);
  const float* Bgs = (const float*)(dsm + BGS);
  const float b4v  = ((const float*)(dsm + B4S))[0];

  // lane bookkeeping
  const int lane = tid & 31, wrp = tid >> 5;
  const int q = lane & 3, g = lane >> 2;
  const int u = lane & 7, tt = lane >> 3;
  const int m0 = wrp * 16;
  const int ar = m0 + u + (tt & 1) * 8;       // A ldmatrix row
  const int akb = (tt >> 1) * 8;              // A ldmatrix k sub-offset
  const int bnu = u + ((tt >> 1) & 1) * 8;    // B ldmatrix n sub-offset
  const int bkb = (tt & 1) * 8;               // B ldmatrix k sub-offset
  const int p = tid >> 1, hf = tid & 1;       // phase-A: 2 threads per point

  for (int tile = blockIdx.x; tile < NTILES; tile += gridDim.x) {
    const int b = tile >> 9;
    const int n_base = (tile & 511) << 7;

    // ================= Phase A: projection + G blend + fourier =================
    {
      const float* pp = points + ((size_t)b * NPTS + n_base + p) * 3;
      const float px = pp[0], py = pp[1], pz = pp[2];
      const float* R = rtm + b * 12;
      const float* K = kmat + b * 9;
      float c0v = R[0]*px + R[1]*py + R[2]*pz  + R[3];
      float c1v = R[4]*px + R[5]*py + R[6]*pz  + R[7];
      float c2v = R[8]*px + R[9]*py + R[10]*pz + R[11];
      float i0 = K[0]*c0v + K[1]*c1v + K[2]*c2v;
      float i1 = K[3]*c0v + K[4]*c1v + K[5]*c2v;
      float i2 = K[6]*c0v + K[7]*c1v + K[8]*c2v;
      float zz = i2 + 1e-8f;
      float uu = i0 / zz, vv = i1 / zz;
      float valid = (i2 > 0.0f) ? 1.0f : 0.0f;
      float un = (2.0f*uu + 1.0f) / (float)WW - 1.0f;
      float vn = (2.0f*vv + 1.0f) / (float)HH - 1.0f;
      float x = ((un + 1.0f) * (float)WW - 1.0f) * 0.5f;
      float y = ((vn + 1.0f) * (float)HH - 1.0f) * 0.5f;
      float x0f = floorf(x), y0f = floorf(y);
      float fx = x - x0f, fy = y - y0f;
      int ix0 = (int)x0f, iy0 = (int)y0f, ix1 = ix0 + 1, iy1 = iy0 + 1;
      float tw[4];
      tw[0] = (1.0f-fx)*(1.0f-fy)*valid;
      tw[1] = fx*(1.0f-fy)*valid;
      tw[2] = (1.0f-fx)*fy*valid;
      tw[3] = fx*fy*valid;
      int to[4];
      to[0] = (((unsigned)ix0 < WW) && ((unsigned)iy0 < HH)) ? (iy0*WW+ix0) : -1;
      to[1] = (((unsigned)ix1 < WW) && ((unsigned)iy0 < HH)) ? (iy0*WW+ix1) : -1;
      to[2] = (((unsigned)ix0 < WW) && ((unsigned)iy1 < HH)) ? (iy1*WW+ix0) : -1;
      to[3] = (((unsigned)ix1 < WW) && ((unsigned)iy1 < HH)) ? (iy1*WW+ix1) : -1;

      // G blend: this thread does 32 of 64 cols
      float ga[32];
#pragma unroll
      for (int j = 0; j < 32; j++) ga[j] = 0.f;
      const float* Gb = g_G + (size_t)b * HWSZ * 64 + hf * 32;
#pragma unroll
      for (int t = 0; t < 4; t++) {
        if (to[t] >= 0) {
          const float4* gp = (const float4*)(Gb + (size_t)to[t] * 64);
          const float w = tw[t];
#pragma unroll
          for (int j = 0; j < 8; j++) {
            float4 v = gp[j];
            ga[4*j]   = fmaf(w, v.x, ga[4*j]);
            ga[4*j+1] = fmaf(w, v.y, ga[4*j+1]);
            ga[4*j+2] = fmaf(w, v.z, ga[4*j+2]);
            ga[4*j+3] = fmaf(w, v.w, ga[4*j+3]);
          }
        }
      }
      float* gs = (float*)(dsm + GSS) + p * 68 + hf * 32;
#pragma unroll
      for (int j = 0; j < 8; j++)
        *(float4*)(gs + 4*j) = make_float4(ga[4*j], ga[4*j+1], ga[4*j+2], ga[4*j+3]);

      // Fourier: 32 of 64 m values; A cols: m -> sin, 64+m -> cos
#pragma unroll
      for (int mg = 0; mg < 4; mg++) {
        const int mb = hf * 32 + mg * 8;
        uint32_t sH[4], sL[4], cH[4], cL[4];
#pragma unroll
        for (int i = 0; i < 4; i++) {
          int m1 = mb + 2*i, m2 = mb + 2*i + 1;
          float pr1 = px*Bgs[3*m1] + py*Bgs[3*m1+1] + pz*Bgs[3*m1+2];
          float pr2 = px*Bgs[3*m2] + py*Bgs[3*m2+1] + pz*Bgs[3*m2+2];
          hilo(__sinf(pr1), __sinf(pr2), sH[i], sL[i]);
          hilo(__cosf(pr1), __cosf(pr2), cH[i], cL[i]);
        }
        const int js = 4*hf + mg;              // sin chunk; cos chunk = 8 + js
        const uint32_t offS = (uint32_t)((p << 4) + (js ^ (p & 7))) * 16u;
        const uint32_t offC = (uint32_t)((p << 4) + ((8 + js) ^ (p & 7))) * 16u;
        *(uint4*)(dsm + AHS + offS) = make_uint4(sH[0], sH[1], sH[2], sH[3]);
        *(uint4*)(dsm + ALS + offS) = make_uint4(sL[0], sL[1], sL[2], sL[3]);
        *(uint4*)(dsm + AHS + offC) = make_uint4(cH[0], cH[1], cH[2], cH[3]);
        *(uint4*)(dsm + ALS + offC) = make_uint4(cL[0], cL[1], cL[2], cL[3]);
      }
    }
    __syncthreads();

    // ================= Phase B: per-warp MLP on tensor cores =================
    {
      float d[8][4];
      // init accumulator from G blend (f32, full precision img contribution)
      const float* gsr = (const float*)(dsm + GSS);
#pragma unroll
      for (int j = 0; j < 8; j++) {
        float2 v0 = *(const float2*)(gsr + (m0 + g) * 68 + 8*j + 2*q);
        float2 v1 = *(const float2*)(gsr + (m0 + g + 8) * 68 + 8*j + 2*q);
        d[j][0] = v0.x; d[j][1] = v0.y; d[j][2] = v1.x; d[j][3] = v1.y;
      }
      // Layer 1 fourier half: K=128
#pragma unroll
      for (int s = 0; s < 8; s++) {
        const int k0 = s * 16;
        const int kcA = k0 + akb;
        uint32_t ah[4], al[4];
        const uint32_t aoff = (uint32_t)((ar << 4) + ((kcA >> 3) ^ (ar & 7))) * 16u;
        LDSM4(ah, sb + AHS + aoff);
        LDSM4(al, sb + ALS + aoff);
        const int kch = (k0 + bkb) >> 3;
#pragma unroll
        for (int jp = 0; jp < 4; jp++) {
          const int n = jp * 16 + bnu;
          const uint32_t woff = (uint32_t)((n << 4) + (kch ^ (n & 7))) * 16u;
          uint32_t wh[4], wl[4];
          LDSM4(wh, sb + W1FH + woff);
          LDSM4(wl, sb + W1FL + woff);
          MMA(d[2*jp],   ah, wh[0], wh[1]);
          MMA(d[2*jp+1], ah, wh[2], wh[3]);
          MMA(d[2*jp],   al, wh[0], wh[1]);
          MMA(d[2*jp+1], al, wh[2], wh[3]);
          MMA(d[2*jp],   ah, wl[0], wl[1]);
          MMA(d[2*jp+1], ah, wl[2], wl[3]);
        }
      }
      // chain layers 2, 3 in registers
      uint32_t ah2[4][4], al2[4][4];
      build_afr(d, b1s, q, ah2, al2);
      layer64(d, ah2, al2, sb, W2HS, W2LS, bnu, bkb);
      build_afr(d, b2s, q, ah2, al2);
      layer64(d, ah2, al2, sb, W3HS, W3LS, bnu, bkb);
      // Layer 4: dot with W4 + b4
      float s0 = 0.f, s1 = 0.f;
#pragma unroll
      for (int j = 0; j < 8; j++) {
        float ba = b3s[8*j+2*q], bb = b3s[8*j+2*q+1];
        float wa = W4s[8*j+2*q], wb = W4s[8*j+2*q+1];
        s0 += fmaxf(d[j][0]+ba, 0.f)*wa + fmaxf(d[j][1]+bb, 0.f)*wb;
        s1 += fmaxf(d[j][2]+ba, 0.f)*wa + fmaxf(d[j][3]+bb, 0.f)*wb;
      }
      s0 += __shfl_xor_sync(0xFFFFFFFFu, s0, 1);
      s0 += __shfl_xor_sync(0xFFFFFFFFu, s0, 2);
      s1 += __shfl_xor_sync(0xFFFFFFFFu, s1, 1);
      s1 += __shfl_xor_sync(0xFFFFFFFFu, s1, 2);
      if (q == 0) {
        out[(size_t)b * NPTS + n_base + m0 + g]     = s0 + b4v;
        out[(size_t)b * NPTS + n_base + m0 + g + 8] = s1 + b4v;
      }
    }
    __syncthreads();
  }
}

// ---------------------------------------------------------------------------
extern "C" void kernel_launch(void* const* d_in, const int* in_sizes, int n_in,
                              void* d_out, int out_size) {
  const float* features = (const float*)d_in[0];
  const float* points   = (const float*)d_in[1];
  const float* kmat     = (const float*)d_in[2];
  const float* rtm      = (const float*)d_in[3];
  const float* Bg       = (const float*)d_in[4];
  const float* W1       = (const float*)d_in[5];
  const float* b1       = (const float*)d_in[6];
  const float* W2       = (const float*)d_in[7];
  const float* b2       = (const float*)d_in[8];
  const float* W3       = (const float*)d_in[9];
  const float* b3       = (const float*)d_in[10];
  const float* W4       = (const float*)d_in[11];
  const float* b4       = (const float*)d_in[12];
  float* out            = (float*)d_out;

  cudaFuncSetAttribute(g_precomp_kernel, cudaFuncAttributeMaxDynamicSharedMemorySize, 98304);
  cudaFuncSetAttribute(decoder_kernel,   cudaFuncAttributeMaxDynamicSharedMemorySize, SMEMB);

  g_precomp_kernel<<<196, THREADS, 98304>>>(features, W1);

  int dev = 0, sms = 148;
  cudaGetDevice(&dev);
  cudaDeviceGetAttribute(&sms, cudaDevAttrMultiProcessorCount, dev);
  if (sms <= 0) sms = 148;

  decoder_kernel<<<sms, THREADS, SMEMB>>>(
      points, kmat, rtm, Bg, W1, b1, W2, b2, W3, b3, W4, b4, out);
}

// round 10
// speedup vs baseline: 4.7959x; 1.8860x over previous
#include <cuda_runtime.h>
#include <cuda_bf16.h>
#include <math.h>
#include <stdint.h>

#define HH 56
#define WW 56
#define HWSZ 3136
#define NB 8
#define NPTS 65536
#define THREADS 256
#define NCHUNKS 16384          // 524288 points / 32 per warp-chunk

// Precomputed G[b][hw][64] = sum_c feat[b][c][hw] * W1[c][n]  (img half of layer 1)
__device__ float g_G[NB * HWSZ * 64];

extern __shared__ char dsm[];

// ---------------- smem map (decoder), byte offsets ----------------
#define W1FH 0          // [64 n][128 k] bf16 hi, swizzled, 16 chunks/row
#define W1FL 16384
#define W2HS 32768      // [64][64] bf16, 8 chunks/row
#define W2LS 40960
#define W3HS 49152
#define W3LS 57344
#define B1S  65536
#define B2S  65792
#define B3S  66048
#define W4S  66304
#define B4S  66560
#define BGS  66576      // 192 floats = 768B
#define GB_OFF 67360    // per-warp G staging: 8 warps x 32 pts x 68 f32
#define SMEMB (GB_OFF + 8 * 32 * 68 * 4)   // 136992

#define LDSM4(R, A) asm volatile("ldmatrix.sync.aligned.m8n8.x4.shared.b16 {%0,%1,%2,%3}, [%4];" \
  : "=r"((R)[0]), "=r"((R)[1]), "=r"((R)[2]), "=r"((R)[3]) : "r"(A))

#define MMA(D, A, B0, B1) asm volatile( \
  "mma.sync.aligned.m16n8k16.row.col.f32.bf16.bf16.f32 {%0,%1,%2,%3}, {%4,%5,%6,%7}, {%8,%9}, {%0,%1,%2,%3};" \
  : "+f"((D)[0]), "+f"((D)[1]), "+f"((D)[2]), "+f"((D)[3]) \
  : "r"((A)[0]), "r"((A)[1]), "r"((A)[2]), "r"((A)[3]), "r"(B0), "r"(B1))

__device__ __forceinline__ void hilo(float a, float b, uint32_t& h, uint32_t& l) {
  __nv_bfloat16 ha = __float2bfloat16(a), hb = __float2bfloat16(b);
  __nv_bfloat162 hp; hp.x = ha; hp.y = hb;
  __nv_bfloat162 lp;
  lp.x = __float2bfloat16(a - __bfloat162float(ha));
  lp.y = __float2bfloat16(b - __bfloat162float(hb));
  h = *(uint32_t*)&hp; l = *(uint32_t*)&lp;
}

// C frags -> next-layer A frags (hi/lo), bias + relu. Verified layout (R7).
__device__ __forceinline__ void build_afr(const float d[8][4], const float* bs, int q,
                                          uint32_t ah[4][4], uint32_t al[4][4]) {
#pragma unroll
  for (int kk = 0; kk < 4; kk++) {
    const int j0 = 2 * kk, j1 = 2 * kk + 1;
    float ba = bs[8*j0+2*q], bb = bs[8*j0+2*q+1];
    float bc = bs[8*j1+2*q], bd = bs[8*j1+2*q+1];
    hilo(fmaxf(d[j0][0]+ba,0.f), fmaxf(d[j0][1]+bb,0.f), ah[kk][0], al[kk][0]);
    hilo(fmaxf(d[j0][2]+ba,0.f), fmaxf(d[j0][3]+bb,0.f), ah[kk][1], al[kk][1]);
    hilo(fmaxf(d[j1][0]+bc,0.f), fmaxf(d[j1][1]+bd,0.f), ah[kk][2], al[kk][2]);
    hilo(fmaxf(d[j1][2]+bc,0.f), fmaxf(d[j1][3]+bd,0.f), ah[kk][3], al[kk][3]);
  }
}

// 64x64 layer for TWO m-tiles sharing each W ldmatrix.
__device__ __forceinline__ void layer64x2(float d[2][8][4],
                                          const uint32_t ah[2][4][4], const uint32_t al[2][4][4],
                                          uint32_t sb, uint32_t baseH, uint32_t baseL,
                                          int bnu, int bkb) {
#pragma unroll
  for (int mt = 0; mt < 2; mt++)
#pragma unroll
    for (int j = 0; j < 8; j++)
#pragma unroll
      for (int e = 0; e < 4; e++) d[mt][j][e] = 0.f;
#pragma unroll
  for (int kk = 0; kk < 4; kk++) {
    const int kch = (kk * 16 + bkb) >> 3;
#pragma unroll
    for (int jp = 0; jp < 4; jp++) {
      const int n = jp * 16 + bnu;
      const uint32_t off = (uint32_t)((n << 3) + (kch ^ (n & 7))) * 16u;
      uint32_t wh[4], wl[4];
      LDSM4(wh, sb + baseH + off);
      LDSM4(wl, sb + baseL + off);
#pragma unroll
      for (int mt = 0; mt < 2; mt++) {
        MMA(d[mt][2*jp],   ah[mt][kk], wh[0], wh[1]);
        MMA(d[mt][2*jp+1], ah[mt][kk], wh[2], wh[3]);
        MMA(d[mt][2*jp],   al[mt][kk], wh[0], wh[1]);
        MMA(d[mt][2*jp+1], al[mt][kk], wh[2], wh[3]);
        MMA(d[mt][2*jp],   ah[mt][kk], wl[0], wl[1]);
        MMA(d[mt][2*jp+1], ah[mt][kk], wl[2], wl[3]);
      }
    }
  }
}

// ---------------------------------------------------------------------------
// Kernel 1: G precompute. grid = 196, block = 256. dyn smem 98304.
// ---------------------------------------------------------------------------
__global__ __launch_bounds__(THREADS, 1)
void g_precomp_kernel(const float* __restrict__ feat, const float* __restrict__ W1) {
  float* fs = (float*)dsm;          // [128 c][128 row]
  float* ws = fs + 128 * 128;       // [128 c][64 n]
  const int tid = threadIdx.x;
  const int R0 = blockIdx.x * 128;
  for (int idx = tid; idx < 128 * 128; idx += THREADS) {
    int c = idx >> 7, i = idx & 127;
    int row = R0 + i, b = row / HWSZ, hw = row - b * HWSZ;
    fs[c * 128 + i] = feat[((size_t)b * 128 + c) * HWSZ + hw];
  }
  for (int idx = tid; idx < 128 * 64; idx += THREADS) ws[idx] = W1[idx];
  __syncthreads();
  const int r0 = (tid >> 3) * 4, c0 = (tid & 7) * 8;
  float acc[4][8];
#pragma unroll
  for (int a = 0; a < 4; a++)
#pragma unroll
    for (int j = 0; j < 8; j++) acc[a][j] = 0.f;
  for (int c = 0; c < 128; c++) {
    float a0 = fs[c*128+r0], a1 = fs[c*128+r0+1], a2 = fs[c*128+r0+2], a3 = fs[c*128+r0+3];
#pragma unroll
    for (int j = 0; j < 8; j++) {
      float w = ws[c*64 + c0 + j];
      acc[0][j] = fmaf(a0, w, acc[0][j]);
      acc[1][j] = fmaf(a1, w, acc[1][j]);
      acc[2][j] = fmaf(a2, w, acc[2][j]);
      acc[3][j] = fmaf(a3, w, acc[3][j]);
    }
  }
#pragma unroll
  for (int a = 0; a < 4; a++) {
    float* dst = g_G + (size_t)(R0 + r0 + a) * 64 + c0;
#pragma unroll
    for (int j = 0; j < 8; j += 4)
      *(float4*)(dst + j) = make_float4(acc[a][j], acc[a][j+1], acc[a][j+2], acc[a][j+3]);
  }
}

// ---------------------------------------------------------------------------
// Kernel 2: persistent decoder — fully warp-independent, 32 pts per warp-iter.
// ---------------------------------------------------------------------------
__global__ __launch_bounds__(THREADS, 1)
void decoder_kernel(const float* __restrict__ points,
                    const float* __restrict__ kmat,
                    const float* __restrict__ rtm,
                    const float* __restrict__ Bg,
                    const float* __restrict__ W1, const float* __restrict__ b1,
                    const float* __restrict__ W2, const float* __restrict__ b2,
                    const float* __restrict__ W3, const float* __restrict__ b3,
                    const float* __restrict__ W4, const float* __restrict__ b4,
                    float* __restrict__ out)
{
  const int tid = threadIdx.x;
  const uint32_t sb = (uint32_t)__cvta_generic_to_shared(dsm);

  // ---- one-time weight prep (identical layouts to R7, which passed) ----
  for (int i = tid; i < 8192; i += THREADS) {        // W1 fourier half -> [n][k] hi/lo
    int k = i >> 6, n = i & 63;
    float v = W1[(128 + k) * 64 + n];
    __nv_bfloat16 h = __float2bfloat16(v);
    uint32_t off = (uint32_t)((n << 4) + ((k >> 3) ^ (n & 7))) * 16u + (uint32_t)(k & 7) * 2u;
    *(__nv_bfloat16*)(dsm + W1FH + off) = h;
    *(__nv_bfloat16*)(dsm + W1FL + off) = __float2bfloat16(v - __bfloat162float(h));
  }
  for (int i = tid; i < 4096; i += THREADS) {        // W2, W3 -> [n][k] hi/lo
    int k = i >> 6, n = i & 63;
    uint32_t off = (uint32_t)((n << 3) + ((k >> 3) ^ (n & 7))) * 16u + (uint32_t)(k & 7) * 2u;
    float v2 = W2[i];
    __nv_bfloat16 h2 = __float2bfloat16(v2);
    *(__nv_bfloat16*)(dsm + W2HS + off) = h2;
    *(__nv_bfloat16*)(dsm + W2LS + off) = __float2bfloat16(v2 - __bfloat162float(h2));
    float v3 = W3[i];
    __nv_bfloat16 h3 = __float2bfloat16(v3);
    *(__nv_bfloat16*)(dsm + W3HS + off) = h3;
    *(__nv_bfloat16*)(dsm + W3LS + off) = __float2bfloat16(v3 - __bfloat162float(h3));
  }
  if (tid < 64) {
    ((float*)(dsm + B1S))[tid] = b1[tid];
    ((float*)(dsm + B2S))[tid] = b2[tid];
    ((float*)(dsm + B3S))[tid] = b3[tid];
    ((float*)(dsm + W4S))[tid] = W4[tid];
  }
  if (tid == 0) ((float*)(dsm + B4S))[0] = b4[0];
  for (int i = tid; i < 192; i += THREADS)
    ((float*)(dsm + BGS))[i] = Bg[i] * 6.283185307179586f;
  __syncthreads();

  const float* b1s = (const float*)(dsm + B1S);
  const float* b2s = (const float*)(dsm + B2S);
  const float* b3s = (const float*)(dsm + B3S);
  const float* W4s = (const float*)(dsm + W4S);
  const float* Bgs = (const float*)(dsm + BGS);
  const float b4v  = ((const float*)(dsm + B4S))[0];

  const int lane = tid & 31, wrp = tid >> 5;
  const int q = lane & 3, g = lane >> 2;
  const int u = lane & 7, tt = lane >> 3;
  const int bnu = u + ((tt >> 1) & 1) * 8;    // W ldmatrix n sub-offset
  const int bkb = (tt & 1) * 8;               // W ldmatrix k sub-offset
  float* gb = (float*)(dsm + GB_OFF) + wrp * (32 * 68);

  const int gwarp = blockIdx.x * 8 + wrp;
  const int wstride = gridDim.x * 8;

  for (int chunk = gwarp; chunk < NCHUNKS; chunk += wstride) {
    const int ptg = chunk << 5;
    const int b = ptg >> 16;
    const int nb = ptg & 65535;

    // ---- projection for own point (lane = point) ----
    const float* pp = points + ((size_t)b * NPTS + nb + lane) * 3;
    const float px = pp[0], py = pp[1], pz = pp[2];
    float tw[4]; int to[4];
    {
      const float* R = rtm + b * 12;
      const float* K = kmat + b * 9;
      float c0v = R[0]*px + R[1]*py + R[2]*pz  + R[3];
      float c1v = R[4]*px + R[5]*py + R[6]*pz  + R[7];
      float c2v = R[8]*px + R[9]*py + R[10]*pz + R[11];
      float i0 = K[0]*c0v + K[1]*c1v + K[2]*c2v;
      float i1 = K[3]*c0v + K[4]*c1v + K[5]*c2v;
      float i2 = K[6]*c0v + K[7]*c1v + K[8]*c2v;
      float zz = i2 + 1e-8f;
      float uu = i0 / zz, vv = i1 / zz;
      float valid = (i2 > 0.0f) ? 1.0f : 0.0f;
      float un = (2.0f*uu + 1.0f) / (float)WW - 1.0f;
      float vn = (2.0f*vv + 1.0f) / (float)HH - 1.0f;
      float x = ((un + 1.0f) * (float)WW - 1.0f) * 0.5f;
      float y = ((vn + 1.0f) * (float)HH - 1.0f) * 0.5f;
      float x0f = floorf(x), y0f = floorf(y);
      float fx = x - x0f, fy = y - y0f;
      int ix0 = (int)x0f, iy0 = (int)y0f, ix1 = ix0 + 1, iy1 = iy0 + 1;
      tw[0] = (1.0f-fx)*(1.0f-fy)*valid;
      tw[1] = fx*(1.0f-fy)*valid;
      tw[2] = (1.0f-fx)*fy*valid;
      tw[3] = fx*fy*valid;
      to[0] = (((unsigned)ix0 < WW) && ((unsigned)iy0 < HH)) ? (iy0*WW+ix0) : -1;
      to[1] = (((unsigned)ix1 < WW) && ((unsigned)iy0 < HH)) ? (iy0*WW+ix1) : -1;
      to[2] = (((unsigned)ix0 < WW) && ((unsigned)iy1 < HH)) ? (iy1*WW+ix0) : -1;
      to[3] = (((unsigned)ix1 < WW) && ((unsigned)iy1 < HH)) ? (iy1*WW+ix1) : -1;
    }

    // ---- G gather: lane blends its own point's 64 cols, stage in gb ----
    __syncwarp();
    {
      const float* Gb = g_G + (size_t)b * HWSZ * 64;
#pragma unroll
      for (int half = 0; half < 2; half++) {
        float4 acc[8];
#pragma unroll
        for (int j = 0; j < 8; j++) acc[j] = make_float4(0.f, 0.f, 0.f, 0.f);
#pragma unroll
        for (int t = 0; t < 4; t++) {
          if (to[t] >= 0) {
            const float4* gp = (const float4*)(Gb + (size_t)to[t] * 64 + half * 32);
            const float w = tw[t];
#pragma unroll
            for (int j = 0; j < 8; j++) {
              float4 v = gp[j];
              acc[j].x = fmaf(w, v.x, acc[j].x);
              acc[j].y = fmaf(w, v.y, acc[j].y);
              acc[j].z = fmaf(w, v.z, acc[j].z);
              acc[j].w = fmaf(w, v.w, acc[j].w);
            }
          }
        }
        float* dst = gb + lane * 68 + half * 32;
#pragma unroll
        for (int j = 0; j < 8; j++) *(float4*)(dst + 4*j) = acc[j];
      }
    }
    __syncwarp();

    // ---- coords of this lane's fragment rows (mt*16 + g, +8) ----
    float rx[4], ry[4], rz[4];
#pragma unroll
    for (int i = 0; i < 4; i++) {
      int r = (i >> 1) * 16 + (i & 1) * 8 + g;
      rx[i] = __shfl_sync(0xFFFFFFFFu, px, r);
      ry[i] = __shfl_sync(0xFFFFFFFFu, py, r);
      rz[i] = __shfl_sync(0xFFFFFFFFu, pz, r);
    }

    // ---- init accumulators from G (f32 img contribution) ----
    float d[2][8][4];
#pragma unroll
    for (int mt = 0; mt < 2; mt++)
#pragma unroll
      for (int j = 0; j < 8; j++) {
        float2 v0 = *(const float2*)(gb + (mt*16 + g) * 68 + 8*j + 2*q);
        float2 v1 = *(const float2*)(gb + (mt*16 + g + 8) * 68 + 8*j + 2*q);
        d[mt][j][0] = v0.x; d[mt][j][1] = v0.y; d[mt][j][2] = v1.x; d[mt][j][3] = v1.y;
      }

    // ---- layer 1 fourier half (K=128): register-built A frags ----
#pragma unroll
    for (int sp = 0; sp < 4; sp++) {
      const int mA = sp * 16 + 2 * q;
      const int mB = mA + 8;
      float g0x = Bgs[3*mA],     g0y = Bgs[3*mA+1],     g0z = Bgs[3*mA+2];
      float g1x = Bgs[3*mA+3],   g1y = Bgs[3*mA+4],     g1z = Bgs[3*mA+5];
      float g2x = Bgs[3*mB],     g2y = Bgs[3*mB+1],     g2z = Bgs[3*mB+2];
      float g3x = Bgs[3*mB+3],   g3y = Bgs[3*mB+4],     g3z = Bgs[3*mB+5];
      uint32_t aS[2][4], aSl[2][4], aC[2][4], aCl[2][4];
#pragma unroll
      for (int mt = 0; mt < 2; mt++) {
#pragma unroll
        for (int rr = 0; rr < 2; rr++) {
          const float X = rx[mt*2+rr], Y = ry[mt*2+rr], Z = rz[mt*2+rr];
          float p0 = X*g0x + Y*g0y + Z*g0z;
          float p1 = X*g1x + Y*g1y + Z*g1z;
          float p2 = X*g2x + Y*g2y + Z*g2z;
          float p3 = X*g3x + Y*g3y + Z*g3z;
          hilo(__sinf(p0), __sinf(p1), aS[mt][rr],   aSl[mt][rr]);
          hilo(__sinf(p2), __sinf(p3), aS[mt][2+rr], aSl[mt][2+rr]);
          hilo(__cosf(p0), __cosf(p1), aC[mt][rr],   aCl[mt][rr]);
          hilo(__cosf(p2), __cosf(p3), aC[mt][2+rr], aCl[mt][2+rr]);
        }
      }
      const int kchS = (sp * 16 + bkb) >> 3;
      const int kchC = (64 + sp * 16 + bkb) >> 3;
#pragma unroll
      for (int jp = 0; jp < 4; jp++) {
        const int n = jp * 16 + bnu;
        uint32_t wh[4], wl[4];
        const uint32_t offS = (uint32_t)((n << 4) + (kchS ^ (n & 7))) * 16u;
        LDSM4(wh, sb + W1FH + offS);
        LDSM4(wl, sb + W1FL + offS);
#pragma unroll
        for (int mt = 0; mt < 2; mt++) {
          MMA(d[mt][2*jp],   aS[mt],  wh[0], wh[1]);
          MMA(d[mt][2*jp+1], aS[mt],  wh[2], wh[3]);
          MMA(d[mt][2*jp],   aSl[mt], wh[0], wh[1]);
          MMA(d[mt][2*jp+1], aSl[mt], wh[2], wh[3]);
          MMA(d[mt][2*jp],   aS[mt],  wl[0], wl[1]);
          MMA(d[mt][2*jp+1], aS[mt],  wl[2], wl[3]);
        }
        const uint32_t offC = (uint32_t)((n << 4) + (kchC ^ (n & 7))) * 16u;
        LDSM4(wh, sb + W1FH + offC);
        LDSM4(wl, sb + W1FL + offC);
#pragma unroll
        for (int mt = 0; mt < 2; mt++) {
          MMA(d[mt][2*jp],   aC[mt],  wh[0], wh[1]);
          MMA(d[mt][2*jp+1], aC[mt],  wh[2], wh[3]);
          MMA(d[mt][2*jp],   aCl[mt], wh[0], wh[1]);
          MMA(d[mt][2*jp+1], aCl[mt], wh[2], wh[3]);
          MMA(d[mt][2*jp],   aC[mt],  wl[0], wl[1]);
          MMA(d[mt][2*jp+1], aC[mt],  wl[2], wl[3]);
        }
      }
    }

    // ---- layers 2, 3 chained in registers, W shared across both m-tiles ----
    {
      uint32_t ah[2][4][4], al[2][4][4];
      build_afr(d[0], b1s, q, ah[0], al[0]);
      build_afr(d[1], b1s, q, ah[1], al[1]);
      layer64x2(d, ah, al, sb, W2HS, W2LS, bnu, bkb);
      build_afr(d[0], b2s, q, ah[0], al[0]);
      build_afr(d[1], b2s, q, ah[1], al[1]);
      layer64x2(d, ah, al, sb, W3HS, W3LS, bnu, bkb);
    }

    // ---- layer 4 + store ----
#pragma unroll
    for (int mt = 0; mt < 2; mt++) {
      float s0 = 0.f, s1 = 0.f;
#pragma unroll
      for (int j = 0; j < 8; j++) {
        float ba = b3s[8*j+2*q], bb = b3s[8*j+2*q+1];
        float wa = W4s[8*j+2*q], wb = W4s[8*j+2*q+1];
        s0 += fmaxf(d[mt][j][0]+ba, 0.f)*wa + fmaxf(d[mt][j][1]+bb, 0.f)*wb;
        s1 += fmaxf(d[mt][j][2]+ba, 0.f)*wa + fmaxf(d[mt][j][3]+bb, 0.f)*wb;
      }
      s0 += __shfl_xor_sync(0xFFFFFFFFu, s0, 1);
      s0 += __shfl_xor_sync(0xFFFFFFFFu, s0, 2);
      s1 += __shfl_xor_sync(0xFFFFFFFFu, s1, 1);
      s1 += __shfl_xor_sync(0xFFFFFFFFu, s1, 2);
      if (q == 0) {
        out[(size_t)b * NPTS + nb + mt*16 + g]     = s0 + b4v;
        out[(size_t)b * NPTS + nb + mt*16 + g + 8] = s1 + b4v;
      }
    }
    __syncwarp();
  }
}

// ---------------------------------------------------------------------------
extern "C" void kernel_launch(void* const* d_in, const int* in_sizes, int n_in,
                              void* d_out, int out_size) {
  const float* features = (const float*)d_in[0];
  const float* points   = (const float*)d_in[1];
  const float* kmat     = (const float*)d_in[2];
  const float* rtm      = (const float*)d_in[3];
  const float* Bg       = (const float*)d_in[4];
  const float* W1       = (const float*)d_in[5];
  const float* b1       = (const float*)d_in[6];
  const float* W2       = (const float*)d_in[7];
  const float* b2       = (const float*)d_in[8];
  const float* W3       = (const float*)d_in[9];
  const float* b3       = (const float*)d_in[10];
  const float* W4       = (const float*)d_in[11];
  const float* b4       = (const float*)d_in[12];
  float* out            = (float*)d_out;

  cudaFuncSetAttribute(g_precomp_kernel, cudaFuncAttributeMaxDynamicSharedMemorySize, 98304);
  cudaFuncSetAttribute(decoder_kernel,   cudaFuncAttributeMaxDynamicSharedMemorySize, SMEMB);

  g_precomp_kernel<<<196, THREADS, 98304>>>(features, W1);

  int dev = 0, sms = 148;
  cudaGetDevice(&dev);
  cudaDeviceGetAttribute(&sms, cudaDevAttrMultiProcessorCount, dev);
  if (sms <= 0) sms = 148;

  decoder_kernel<<<sms, THREADS, SMEMB>>>(
      points, kmat, rtm, Bg, W1, b1, W2, b2, W3, b3, W4, b4, out);
}